// round 2
// baseline (speedup 1.0000x reference)
#include <cuda_runtime.h>
#include <cstdint>

#define DIM   384
#define DIM4  (DIM / 4)
#define MAXM  16
#define MAXN  50000
#define NB    65536                      // buckets per row (top 16 bits of sortable key)
#define PAV_TPB 256
#define LMAX ((MAXN + PAV_TPB - 1) / PAV_TPB)   // 196
#define SCAN_ELEMS 16
#define SCAN_TPB   256
#define SCAN_CHUNK (SCAN_ELEMS * SCAN_TPB)      // 4096

// ---- static device scratch (no allocations allowed) ----
__device__ float    g_qn[MAXM * DIM];
__device__ unsigned g_key   [MAXM * MAXN];
__device__ int      g_hist  [MAXM * NB];
__device__ int      g_start [MAXM * NB + 1];
__device__ int      g_cursor[MAXM * NB];
__device__ int      g_bsum  [1024];
__device__ int      g_slot  [MAXM * MAXN];
__device__ int      g_sorted[MAXM * MAXN];
__device__ double   g_ssum[MAXM * MAXN];
__device__ int      g_scnt[MAXM * MAXN];
__device__ int      g_sbnd[MAXM * MAXN];
__device__ double   g_csum[MAXM * MAXN];
__device__ int      g_ccnt[MAXM * MAXN];

// ---------------- query normalization ----------------
__global__ void qnorm_kernel(const float* __restrict__ q, int M) {
    int row = blockIdx.x;
    float ss = 0.f;
    for (int i = threadIdx.x; i < DIM; i += blockDim.x) {
        float v = q[row * DIM + i];
        ss += v * v;
    }
    __shared__ float red[128];
    red[threadIdx.x] = ss;
    __syncthreads();
    for (int s = 64; s > 0; s >>= 1) {
        if (threadIdx.x < s) red[threadIdx.x] += red[threadIdx.x + s];
        __syncthreads();
    }
    float inv = 1.f / fmaxf(sqrtf(red[0]), 1e-12f);
    for (int i = threadIdx.x; i < DIM; i += blockDim.x)
        g_qn[row * DIM + i] = q[row * DIM + i] * inv;
}

// ---------------- cosine similarity GEMM ----------------
#define DPW 4
__global__ void sim_kernel(const float4* __restrict__ corpus4,
                           float* __restrict__ sims, int M, int N) {
    __shared__ float4 qs[MAXM * DIM4];   // 24 KB
    for (int i = threadIdx.x; i < MAXM * DIM4; i += blockDim.x)
        qs[i] = ((const float4*)g_qn)[i];
    __syncthreads();

    int warp = threadIdx.x >> 5, lane = threadIdx.x & 31;
    int dbase = (blockIdx.x * 8 + warp) * DPW;

    float acc[DPW][16];
    float ss[DPW];
#pragma unroll
    for (int d = 0; d < DPW; d++) {
        ss[d] = 0.f;
#pragma unroll
        for (int q = 0; q < 16; q++) acc[d][q] = 0.f;
    }

    bool full = (dbase + DPW <= N);
    for (int k = lane; k < DIM4; k += 32) {
        float4 v[DPW];
#pragma unroll
        for (int d = 0; d < DPW; d++) {
            int doc = dbase + d;
            if (full || doc < N)
                v[d] = corpus4[(size_t)doc * DIM4 + k];
            else
                v[d] = make_float4(0.f, 0.f, 0.f, 0.f);
            ss[d] += v[d].x * v[d].x + v[d].y * v[d].y +
                     v[d].z * v[d].z + v[d].w * v[d].w;
        }
#pragma unroll
        for (int q = 0; q < 16; q++) {
            float4 qq = qs[q * DIM4 + k];
#pragma unroll
            for (int d = 0; d < DPW; d++) {
                acc[d][q] += qq.x * v[d].x + qq.y * v[d].y +
                             qq.z * v[d].z + qq.w * v[d].w;
            }
        }
    }

#pragma unroll
    for (int off = 16; off; off >>= 1) {
#pragma unroll
        for (int d = 0; d < DPW; d++) {
            ss[d] += __shfl_xor_sync(0xffffffffu, ss[d], off);
#pragma unroll
            for (int q = 0; q < 16; q++)
                acc[d][q] += __shfl_xor_sync(0xffffffffu, acc[d][q], off);
        }
    }

    __shared__ float st[8 * DPW * 16];
    if (lane == 0) {
#pragma unroll
        for (int d = 0; d < DPW; d++) {
            float inv = 1.f / fmaxf(sqrtf(ss[d]), 1e-12f);
#pragma unroll
            for (int q = 0; q < 16; q++)
                st[(warp * DPW + d) * 16 + q] = acc[d][q] * inv;
        }
    }
    __syncthreads();

    int blockbase = blockIdx.x * (8 * DPW);
    for (int i = threadIdx.x; i < 8 * DPW * M; i += blockDim.x) {
        int q = i / (8 * DPW);
        int w = i - q * (8 * DPW);
        int doc = blockbase + w;
        if (doc < N) sims[(size_t)q * N + doc] = st[w * 16 + q];
    }
}

// ---------------- key + histogram ----------------
__global__ void keyfill_kernel(const float* __restrict__ sims, int M, int N) {
    int i = blockIdx.x * blockDim.x + threadIdx.x;
    if (i < M * N) {
        int row = i / N;
        unsigned u = __float_as_uint(sims[i]);
        u = (u & 0x80000000u) ? ~u : (u | 0x80000000u);   // ascending-sortable
        g_key[i] = u;
        atomicAdd(&g_hist[row * NB + (u >> 16)], 1);
    }
}

// ---------------- 3-kernel exclusive scan over M*NB counters ----------------
__global__ void scan1_kernel(int C) {
    __shared__ int sh[SCAN_TPB];
    int base = blockIdx.x * SCAN_CHUNK + threadIdx.x * SCAN_ELEMS;
    int v[SCAN_ELEMS];
    int s = 0;
#pragma unroll
    for (int e = 0; e < SCAN_ELEMS; e++) {
        int idx = base + e;
        v[e] = (idx < C) ? g_hist[idx] : 0;
        s += v[e];
    }
    sh[threadIdx.x] = s;
    __syncthreads();
    // Hillis-Steele inclusive scan
    for (int off = 1; off < SCAN_TPB; off <<= 1) {
        int t = (threadIdx.x >= off) ? sh[threadIdx.x - off] : 0;
        __syncthreads();
        sh[threadIdx.x] += t;
        __syncthreads();
    }
    int excl = sh[threadIdx.x] - s;   // exclusive prefix of this thread
    if (threadIdx.x == SCAN_TPB - 1) g_bsum[blockIdx.x] = sh[SCAN_TPB - 1];
    int run = excl;
#pragma unroll
    for (int e = 0; e < SCAN_ELEMS; e++) {
        int idx = base + e;
        if (idx < C) g_start[idx] = run;
        run += v[e];
    }
}

__global__ void scan2_kernel(int nblocks) {
    __shared__ int sh[1024];
    int t = threadIdx.x;
    int val = (t < nblocks) ? g_bsum[t] : 0;
    sh[t] = val;
    __syncthreads();
    for (int off = 1; off < 1024; off <<= 1) {
        int tv = (t >= off) ? sh[t - off] : 0;
        __syncthreads();
        sh[t] += tv;
        __syncthreads();
    }
    if (t < nblocks) g_bsum[t] = sh[t] - val;   // exclusive
}

__global__ void scan3_kernel(int C, int total) {
    int i = blockIdx.x * blockDim.x + threadIdx.x;
    if (i < C) {
        int v = g_start[i] + g_bsum[i / SCAN_CHUNK];
        g_start[i] = v;
        g_cursor[i] = v;
    }
    if (i == 0) g_start[C] = total;
}

// ---------------- scatter into buckets (order within bucket arbitrary) ------
__global__ void scatter_kernel(int M, int N) {
    int i = blockIdx.x * blockDim.x + threadIdx.x;
    if (i < M * N) {
        int row = i / N;
        unsigned u = g_key[i];
        int pos = atomicAdd(&g_cursor[row * NB + (u >> 16)], 1);
        g_slot[pos] = i - row * N;   // col
    }
}

// ---------------- deterministic in-bucket ordering ----------------
__global__ void order_kernel(int M, int N) {
    int i = blockIdx.x * blockDim.x + threadIdx.x;
    if (i >= M * N) return;
    int row = i / N;
    int col = i - row * N;
    unsigned u = g_key[i];
    int rb = row * NB + (u >> 16);
    int base = g_start[rb];
    int cnt  = g_start[rb + 1] - base;
    int rank = 0;
    if (cnt > 1) {
        const unsigned* krow = g_key + (size_t)row * N;
        for (int k = 0; k < cnt; k++) {
            int c2 = g_slot[base + k];
            unsigned u2 = krow[c2];
            rank += (u2 < u) | ((u2 == u) & (c2 < col));
        }
    }
    g_sorted[base + rank] = col;
}

// ---------------- parallel PAV (nonincreasing isotonic regression) ----------
__global__ void pav_kernel(const float* __restrict__ sims,
                           float* __restrict__ ranks, int M, int N) {
    int row = blockIdx.x;
    const int* sorted = g_sorted + (size_t)row * N;
    const float* srow = sims + (size_t)row * N;
    double* csum = g_csum + (size_t)row * N;
    int*    ccnt = g_ccnt + (size_t)row * N;
    double* ssum = g_ssum + (size_t)row * N;
    int*    scnt = g_scnt + (size_t)row * N;
    int*    sbnd = g_sbnd + (size_t)row * N;

    int t = threadIdx.x;
    int L = (N + PAV_TPB - 1) / PAV_TPB;
    int j0 = min(t * L, N);
    int j1 = min(j0 + L, N);

    __shared__ int    snb[PAV_TPB];
    __shared__ double s1sum[PAV_TPB];
    __shared__ int    s1cnt[PAV_TPB];
    __shared__ int    sP;

    // --- phase 1: chunk PAV, register-cached stack top ---
    double lsum[LMAX];
    int    lcnt[LMAX];
    double topS = 0.0;
    int    topC = 0;
    int p = 0;
    for (int j = j0; j < j1; j++) {
        double cs = -10.0 * (double)srow[sorted[j]] - (double)(N - j);
        int cc = 1;
        while (p > 0 && topS * (double)cc < cs * (double)topC) {
            cs += topS; cc += topC; p--;
            if (p > 0) { topS = lsum[p - 1]; topC = lcnt[p - 1]; }
        }
        if (p > 0) { lsum[p - 1] = topS; lcnt[p - 1] = topC; }
        topS = cs; topC = cc; p++;
    }
    if (p > 0) { lsum[p - 1] = topS; lcnt[p - 1] = topC; }
    for (int b = 0; b < p; b++) { csum[j0 + b] = lsum[b]; ccnt[j0 + b] = lcnt[b]; }
    snb[t] = p;
    if (p >= 1) { s1sum[t] = lsum[0]; s1cnt[t] = lcnt[0]; }
    __syncthreads();

    // --- phase 2: sequential merge of chunk block lists ---
    if (t == 0) {
        int P = 0;
        double TS = 0.0; int TC = 0;
        for (int tt = 0; tt < PAV_TPB; tt++) {
            int nb = snb[tt];
            int bbase = tt * L;
            for (int b = 0; b < nb; b++) {
                double cs; int cc;
                if (b == 0) { cs = s1sum[tt]; cc = s1cnt[tt]; }
                else        { cs = csum[bbase + b]; cc = ccnt[bbase + b]; }
                while (P > 0 && TS * (double)cc < cs * (double)TC) {
                    cs += TS; cc += TC; P--;
                    if (P > 0) { TS = ssum[P - 1]; TC = scnt[P - 1]; }
                }
                if (P > 0) { ssum[P - 1] = TS; scnt[P - 1] = TC; }
                TS = cs; TC = cc; P++;
            }
        }
        if (P > 0) { ssum[P - 1] = TS; scnt[P - 1] = TC; }
        int acc = 0;
        for (int b = 0; b < P; b++) { acc += scnt[b]; sbnd[b] = acc; }
        sP = P;
    }
    __syncthreads();

    // --- phase 3: per-element dual lookup + scatter primal ---
    int P = sP;
    for (int j = t; j < N; j += PAV_TPB) {
        int lo = 0, hi = P - 1;
        while (lo < hi) {
            int mid = (lo + hi) >> 1;
            if (sbnd[mid] > j) hi = mid; else lo = mid + 1;
        }
        double dual = ssum[lo] / (double)scnt[lo];
        int col = sorted[j];
        double s = -10.0 * (double)srow[col];
        ranks[(size_t)row * N + col] = (float)(s - dual);
    }
}

// ---------------- host launch ----------------
extern "C" void kernel_launch(void* const* d_in, const int* in_sizes, int n_in,
                              void* d_out, int out_size) {
    const float* q      = (const float*)d_in[0];
    const float* corpus = (const float*)d_in[1];
    int M = in_sizes[0] / DIM;   // 16
    int N = in_sizes[1] / DIM;   // 50000
    if (M > MAXM) M = MAXM;
    if (N > MAXN) N = MAXN;

    float* sims  = (float*)d_out;
    float* ranks = sims + (size_t)M * N;

    qnorm_kernel<<<M, 128>>>(q, M);

    int docs_per_block = 8 * DPW;   // 32
    sim_kernel<<<(N + docs_per_block - 1) / docs_per_block, 256>>>(
        (const float4*)corpus, sims, M, N);

    int total = M * N;
    int C = M * NB;

    void* p_hist;
    cudaGetSymbolAddress(&p_hist, g_hist);
    cudaMemsetAsync(p_hist, 0, (size_t)C * sizeof(int));

    keyfill_kernel<<<(total + 255) / 256, 256>>>(sims, M, N);

    int nblocks = (C + SCAN_CHUNK - 1) / SCAN_CHUNK;   // 256 for M=16
    scan1_kernel<<<nblocks, SCAN_TPB>>>(C);
    scan2_kernel<<<1, 1024>>>(nblocks);
    scan3_kernel<<<(C + 255) / 256, 256>>>(C, total);

    scatter_kernel<<<(total + 255) / 256, 256>>>(M, N);
    order_kernel<<<(total + 255) / 256, 256>>>(M, N);

    pav_kernel<<<M, PAV_TPB>>>(sims, ranks, M, N);
}

// round 3
// speedup vs baseline: 1.6354x; 1.6354x over previous
#include <cuda_runtime.h>
#include <cstdint>

#define DIM   384
#define DIM4  (DIM / 4)
#define MAXM  16
#define MAXN  50000
#define NB    4096                       // buckets per row (top 12 bits of sortable key)
#define PAV_TPB 256
#define LMAX ((MAXN + PAV_TPB - 1) / PAV_TPB)   // 196

// ---- static device scratch (no allocations allowed) ----
__device__ float  g_qn[MAXM * DIM];
__device__ int    g_hist[MAXM * NB];     // counts -> exclusive-start cursors (in place)
__device__ int2   g_pair[MAXM * MAXN];   // {.x = float bits of sim, .y = col}, bucket-sorted
__device__ double g_ssum[MAXM * MAXN];
__device__ int    g_scnt[MAXM * MAXN];
__device__ int    g_sbnd[MAXM * MAXN];
__device__ double g_csum[MAXM * MAXN];
__device__ int    g_ccnt[MAXM * MAXN];

__device__ __forceinline__ unsigned sortable(float f) {
    unsigned u = __float_as_uint(f);
    return (u & 0x80000000u) ? ~u : (u | 0x80000000u);   // ascending order
}

// ---------------- query normalization ----------------
__global__ void qnorm_kernel(const float* __restrict__ q, int M) {
    int row = blockIdx.x;
    float ss = 0.f;
    for (int i = threadIdx.x; i < DIM; i += blockDim.x) {
        float v = q[row * DIM + i];
        ss += v * v;
    }
    __shared__ float red[128];
    red[threadIdx.x] = ss;
    __syncthreads();
    for (int s = 64; s > 0; s >>= 1) {
        if (threadIdx.x < s) red[threadIdx.x] += red[threadIdx.x + s];
        __syncthreads();
    }
    float inv = 1.f / fmaxf(sqrtf(red[0]), 1e-12f);
    for (int i = threadIdx.x; i < DIM; i += blockDim.x)
        g_qn[row * DIM + i] = q[row * DIM + i] * inv;
}

// ---------------- cosine similarity GEMM + fused bucket histogram ----------
#define DPW 4
__global__ void sim_kernel(const float4* __restrict__ corpus4,
                           float* __restrict__ sims, int M, int N) {
    __shared__ float4 qs[MAXM * DIM4];   // 24 KB
    for (int i = threadIdx.x; i < MAXM * DIM4; i += blockDim.x)
        qs[i] = ((const float4*)g_qn)[i];
    __syncthreads();

    int warp = threadIdx.x >> 5, lane = threadIdx.x & 31;
    int dbase = (blockIdx.x * 8 + warp) * DPW;

    float acc[DPW][16];
    float ss[DPW];
#pragma unroll
    for (int d = 0; d < DPW; d++) {
        ss[d] = 0.f;
#pragma unroll
        for (int q = 0; q < 16; q++) acc[d][q] = 0.f;
    }

    bool full = (dbase + DPW <= N);
    for (int k = lane; k < DIM4; k += 32) {
        float4 v[DPW];
#pragma unroll
        for (int d = 0; d < DPW; d++) {
            int doc = dbase + d;
            if (full || doc < N)
                v[d] = corpus4[(size_t)doc * DIM4 + k];
            else
                v[d] = make_float4(0.f, 0.f, 0.f, 0.f);
            ss[d] += v[d].x * v[d].x + v[d].y * v[d].y +
                     v[d].z * v[d].z + v[d].w * v[d].w;
        }
#pragma unroll
        for (int q = 0; q < 16; q++) {
            float4 qq = qs[q * DIM4 + k];
#pragma unroll
            for (int d = 0; d < DPW; d++) {
                acc[d][q] += qq.x * v[d].x + qq.y * v[d].y +
                             qq.z * v[d].z + qq.w * v[d].w;
            }
        }
    }

#pragma unroll
    for (int off = 16; off; off >>= 1) {
#pragma unroll
        for (int d = 0; d < DPW; d++) {
            ss[d] += __shfl_xor_sync(0xffffffffu, ss[d], off);
#pragma unroll
            for (int q = 0; q < 16; q++)
                acc[d][q] += __shfl_xor_sync(0xffffffffu, acc[d][q], off);
        }
    }

    __shared__ float st[8 * DPW * 16];   // [doc_in_block][q]
    if (lane == 0) {
#pragma unroll
        for (int d = 0; d < DPW; d++) {
            float inv = 1.f / fmaxf(sqrtf(ss[d]), 1e-12f);
#pragma unroll
            for (int q = 0; q < 16; q++)
                st[(warp * DPW + d) * 16 + q] = acc[d][q] * inv;
        }
    }
    __syncthreads();

    int blockbase = blockIdx.x * (8 * DPW);
    for (int i = threadIdx.x; i < 8 * DPW * M; i += blockDim.x) {
        int q = i / (8 * DPW);
        int w = i - q * (8 * DPW);
        int doc = blockbase + w;
        if (doc < N) {
            float v = st[w * 16 + q];
            sims[(size_t)q * N + doc] = v;
            atomicAdd(&g_hist[q * NB + (sortable(v) >> 20)], 1);
        }
    }
}

// ---------------- per-row exclusive scan over NB counters ----------------
// One block per row. Row base offset = row*N (each row has exactly N elements).
__global__ void scan_kernel(int N) {
    int row = blockIdx.x;
    int t = threadIdx.x;            // 1024 threads, 4 counters each
    int* h = g_hist + row * NB;
    int base = t * 4;
    int v0 = h[base + 0], v1 = h[base + 1], v2 = h[base + 2], v3 = h[base + 3];
    int s = v0 + v1 + v2 + v3;

    __shared__ int sh[1024];
    sh[t] = s;
    __syncthreads();
    for (int off = 1; off < 1024; off <<= 1) {
        int tv = (t >= off) ? sh[t - off] : 0;
        __syncthreads();
        sh[t] += tv;
        __syncthreads();
    }
    int run = row * N + sh[t] - s;   // global exclusive prefix
    h[base + 0] = run;             run += v0;
    h[base + 1] = run;             run += v1;
    h[base + 2] = run;             run += v2;
    h[base + 3] = run;
}

// ---------------- scatter into buckets (within-bucket order arbitrary) ------
__global__ void scatter_kernel(const float* __restrict__ sims, int M, int N) {
    int i = blockIdx.x * blockDim.x + threadIdx.x;
    if (i < M * N) {
        int row = i / N;
        int col = i - row * N;
        float v = sims[i];
        int pos = atomicAdd(&g_hist[row * NB + (sortable(v) >> 20)], 1);
        g_pair[pos] = make_int2(__float_as_int(v), col);
    }
}

// ---------------- parallel PAV (nonincreasing isotonic regression) ----------
// One block per row. Phase 1: per-thread chunk PAV. Phase 2: thread-0 merges
// chunk block lists. Phase 3: binary-search block, scatter primal.
__global__ void pav_kernel(float* __restrict__ ranks, int M, int N) {
    int row = blockIdx.x;
    const int2* pair = g_pair + (size_t)row * N;
    double* csum = g_csum + (size_t)row * N;
    int*    ccnt = g_ccnt + (size_t)row * N;
    double* ssum = g_ssum + (size_t)row * N;
    int*    scnt = g_scnt + (size_t)row * N;
    int*    sbnd = g_sbnd + (size_t)row * N;

    int t = threadIdx.x;
    int L = (N + PAV_TPB - 1) / PAV_TPB;
    int j0 = min(t * L, N);
    int j1 = min(j0 + L, N);

    __shared__ int    snb[PAV_TPB];
    __shared__ double s1sum[PAV_TPB];
    __shared__ int    s1cnt[PAV_TPB];
    __shared__ int    sP;

    // --- phase 1: chunk PAV with register-cached stack top ---
    double lsum[LMAX];
    int    lcnt[LMAX];
    double topS = 0.0;
    int    topC = 0;
    int p = 0;
    for (int j = j0; j < j1; j++) {
        float v = __int_as_float(pair[j].x);
        double cs = -10.0 * (double)v - (double)(N - j);   // y_j = s_j - (n - j)
        int cc = 1;
        while (p > 0 && topS * (double)cc < cs * (double)topC) {
            cs += topS; cc += topC; p--;
            if (p > 0) { topS = lsum[p - 1]; topC = lcnt[p - 1]; }
        }
        if (p > 0) { lsum[p - 1] = topS; lcnt[p - 1] = topC; }
        topS = cs; topC = cc; p++;
    }
    if (p > 0) { lsum[p - 1] = topS; lcnt[p - 1] = topC; }
    for (int b = 0; b < p; b++) { csum[j0 + b] = lsum[b]; ccnt[j0 + b] = lcnt[b]; }
    snb[t] = p;
    if (p >= 1) { s1sum[t] = lsum[0]; s1cnt[t] = lcnt[0]; }
    __syncthreads();

    // --- phase 2: sequential merge of chunk block lists ---
    if (t == 0) {
        int P = 0;
        double TS = 0.0; int TC = 0;
        for (int tt = 0; tt < PAV_TPB; tt++) {
            int nb = snb[tt];
            int bbase = tt * L;
            for (int b = 0; b < nb; b++) {
                double cs; int cc;
                if (b == 0) { cs = s1sum[tt]; cc = s1cnt[tt]; }
                else        { cs = csum[bbase + b]; cc = ccnt[bbase + b]; }
                while (P > 0 && TS * (double)cc < cs * (double)TC) {
                    cs += TS; cc += TC; P--;
                    if (P > 0) { TS = ssum[P - 1]; TC = scnt[P - 1]; }
                }
                if (P > 0) { ssum[P - 1] = TS; scnt[P - 1] = TC; }
                TS = cs; TC = cc; P++;
            }
        }
        if (P > 0) { ssum[P - 1] = TS; scnt[P - 1] = TC; }
        int acc = 0;
        for (int b = 0; b < P; b++) { acc += scnt[b]; sbnd[b] = acc; }
        sP = P;
    }
    __syncthreads();

    // --- phase 3: per-element dual lookup + scatter primal ---
    int P = sP;
    for (int j = t; j < N; j += PAV_TPB) {
        int2 pr = pair[j];
        int lo = 0, hi = P - 1;
        while (lo < hi) {
            int mid = (lo + hi) >> 1;
            if (sbnd[mid] > j) hi = mid; else lo = mid + 1;
        }
        double dual = ssum[lo] / (double)scnt[lo];
        double s = -10.0 * (double)__int_as_float(pr.x);
        ranks[(size_t)row * N + pr.y] = (float)(s - dual);
    }
}

// ---------------- host launch ----------------
extern "C" void kernel_launch(void* const* d_in, const int* in_sizes, int n_in,
                              void* d_out, int out_size) {
    const float* q      = (const float*)d_in[0];
    const float* corpus = (const float*)d_in[1];
    int M = in_sizes[0] / DIM;   // 16
    int N = in_sizes[1] / DIM;   // 50000
    if (M > MAXM) M = MAXM;
    if (N > MAXN) N = MAXN;

    float* sims  = (float*)d_out;
    float* ranks = sims + (size_t)M * N;

    void* p_hist;
    cudaGetSymbolAddress(&p_hist, g_hist);
    cudaMemsetAsync(p_hist, 0, (size_t)M * NB * sizeof(int));

    qnorm_kernel<<<M, 128>>>(q, M);

    int docs_per_block = 8 * DPW;   // 32
    sim_kernel<<<(N + docs_per_block - 1) / docs_per_block, 256>>>(
        (const float4*)corpus, sims, M, N);

    scan_kernel<<<M, 1024>>>(N);

    int total = M * N;
    scatter_kernel<<<(total + 255) / 256, 256>>>(sims, M, N);

    pav_kernel<<<M, PAV_TPB>>>(ranks, M, N);
}

// round 4
// speedup vs baseline: 1.6469x; 1.0070x over previous
#include <cuda_runtime.h>
#include <cstdint>

#define DIM   384
#define DIM4  (DIM / 4)
#define MAXM  16
#define MAXN  50000
#define NB    4096                       // buckets per row (top 12 bits of sortable key)
#define PAV_TPB 256
#define LMAX ((MAXN + PAV_TPB - 1) / PAV_TPB)   // 196

#define TILE_DOCS 32
#define TILE_F4   (TILE_DOCS * DIM4)     // 3072 float4 = 48 KB
#define SIM_TPB   256
#define SIM_BLOCKS 148
#define LD_PER_THR (TILE_F4 / SIM_TPB)   // 12
#define DPW 4
#define SMEM_DYN ((MAXM * DIM4 + 2 * TILE_F4) * (int)sizeof(float4))   // 120 KB

// ---- static device scratch (no allocations allowed) ----
__device__ float  g_qn[MAXM * DIM];
__device__ int    g_hist[MAXM * NB];     // counts -> cursors (in place)
__device__ int2   g_pair[MAXM * MAXN];   // {simbits, col}, bucket-sorted per row
__device__ double g_ssum[MAXM * MAXN];
__device__ int    g_scnt[MAXM * MAXN];
__device__ int    g_sbnd[MAXM * MAXN];
__device__ double g_csum[MAXM * MAXN];
__device__ int    g_ccnt[MAXM * MAXN];

__device__ __forceinline__ unsigned sortable(float f) {
    unsigned u = __float_as_uint(f);
    return (u & 0x80000000u) ? ~u : (u | 0x80000000u);   // ascending order
}

// ---- cp.async helpers ----
__device__ __forceinline__ void cp16(void* smem, const void* gmem) {
    unsigned s = (unsigned)__cvta_generic_to_shared(smem);
    asm volatile("cp.async.cg.shared.global [%0], [%1], 16;\n"
                 :: "r"(s), "l"(gmem) : "memory");
}
__device__ __forceinline__ void cp_commit() {
    asm volatile("cp.async.commit_group;\n" ::: "memory");
}
template <int W>
__device__ __forceinline__ void cp_wait() {
    asm volatile("cp.async.wait_group %0;\n" :: "n"(W) : "memory");
}

// ---------------- query normalization ----------------
__global__ void qnorm_kernel(const float* __restrict__ q, int M) {
    int row = blockIdx.x;
    float ss = 0.f;
    for (int i = threadIdx.x; i < DIM; i += blockDim.x) {
        float v = q[row * DIM + i];
        ss += v * v;
    }
    __shared__ float red[128];
    red[threadIdx.x] = ss;
    __syncthreads();
    for (int s = 64; s > 0; s >>= 1) {
        if (threadIdx.x < s) red[threadIdx.x] += red[threadIdx.x + s];
        __syncthreads();
    }
    float inv = 1.f / fmaxf(sqrtf(red[0]), 1e-12f);
    for (int i = threadIdx.x; i < DIM; i += blockDim.x)
        g_qn[row * DIM + i] = q[row * DIM + i] * inv;
}

// ---------------- cosine similarity GEMM, cp.async double-buffered ---------
__device__ __forceinline__ void sim_prefetch(float4* dst, const float4* __restrict__ corpus4,
                                             int tile, int N) {
    int docbase = tile * TILE_DOCS;
#pragma unroll
    for (int j = 0; j < LD_PER_THR; j++) {
        int idx = threadIdx.x + j * SIM_TPB;
        int d = idx / DIM4;
        int c = idx - d * DIM4;
        int doc = docbase + d;
        if (doc < N) cp16(dst + idx, corpus4 + (size_t)doc * DIM4 + c);
    }
}

extern __shared__ float4 sh4[];   // [0,1536): queries, then 2 x 3072 tile buffers

__global__ void __launch_bounds__(SIM_TPB, 1)
sim_kernel(const float4* __restrict__ corpus4, float* __restrict__ sims,
           int M, int N) {
    float4* qs    = sh4;
    float4* tiles = sh4 + MAXM * DIM4;

    for (int i = threadIdx.x; i < MAXM * DIM4; i += SIM_TPB)
        qs[i] = ((const float4*)g_qn)[i];

    int ntiles = (N + TILE_DOCS - 1) / TILE_DOCS;
    int t0 = blockIdx.x;
    if (t0 < ntiles) sim_prefetch(tiles, corpus4, t0, N);
    cp_commit();

    int warp = threadIdx.x >> 5, lane = threadIdx.x & 31;
    __shared__ float st[8 * DPW * 16];

    int it = 0;
    for (int t = t0; t < ntiles; t += gridDim.x, it++) {
        float4* cur = tiles + (it & 1) * TILE_F4;
        float4* nxt = tiles + ((it + 1) & 1) * TILE_F4;
        int tn = t + gridDim.x;
        if (tn < ntiles) {
            sim_prefetch(nxt, corpus4, tn, N);
            cp_commit();
            cp_wait<1>();
        } else {
            cp_wait<0>();
        }
        __syncthreads();

        // ---- compute 32 docs x 16 queries from SMEM ----
        const float4* vbase = cur + warp * DPW * DIM4;
        float acc[DPW][16];
        float ss[DPW];
#pragma unroll
        for (int d = 0; d < DPW; d++) {
            ss[d] = 0.f;
#pragma unroll
            for (int q = 0; q < 16; q++) acc[d][q] = 0.f;
        }
#pragma unroll
        for (int itk = 0; itk < 3; itk++) {
            int k = lane + itk * 32;
            float4 v[DPW];
#pragma unroll
            for (int d = 0; d < DPW; d++) {
                v[d] = vbase[d * DIM4 + k];
                ss[d] += v[d].x * v[d].x + v[d].y * v[d].y +
                         v[d].z * v[d].z + v[d].w * v[d].w;
            }
#pragma unroll
            for (int q = 0; q < 16; q++) {
                float4 qq = qs[q * DIM4 + k];
#pragma unroll
                for (int d = 0; d < DPW; d++) {
                    acc[d][q] += qq.x * v[d].x + qq.y * v[d].y +
                                 qq.z * v[d].z + qq.w * v[d].w;
                }
            }
        }
#pragma unroll
        for (int off = 16; off; off >>= 1) {
#pragma unroll
            for (int d = 0; d < DPW; d++) {
                ss[d] += __shfl_xor_sync(0xffffffffu, ss[d], off);
#pragma unroll
                for (int q = 0; q < 16; q++)
                    acc[d][q] += __shfl_xor_sync(0xffffffffu, acc[d][q], off);
            }
        }
        if (lane == 0) {
#pragma unroll
            for (int d = 0; d < DPW; d++) {
                float inv = 1.f / fmaxf(sqrtf(ss[d]), 1e-12f);
#pragma unroll
                for (int q = 0; q < 16; q++)
                    st[(warp * DPW + d) * 16 + q] = acc[d][q] * inv;
            }
        }
        __syncthreads();

        int docbase = t * TILE_DOCS;
        for (int i = threadIdx.x; i < TILE_DOCS * M; i += SIM_TPB) {
            int q = i / TILE_DOCS;
            int w = i - q * TILE_DOCS;
            int doc = docbase + w;
            if (doc < N) {
                float v = st[w * 16 + q];
                sims[(size_t)q * N + doc] = v;
                atomicAdd(&g_hist[q * NB + (sortable(v) >> 20)], 1);
            }
        }
        __syncthreads();   // epilogue/compute done before buffer reuse
    }
}

// ---------------- per-row exclusive scan over NB counters ----------------
__global__ void scan_kernel(int N) {
    int row = blockIdx.x;
    int t = threadIdx.x;            // 1024 threads, 4 counters each
    int* h = g_hist + row * NB;
    int base = t * 4;
    int v0 = h[base + 0], v1 = h[base + 1], v2 = h[base + 2], v3 = h[base + 3];
    int s = v0 + v1 + v2 + v3;

    __shared__ int shm[1024];
    shm[t] = s;
    __syncthreads();
    for (int off = 1; off < 1024; off <<= 1) {
        int tv = (t >= off) ? shm[t - off] : 0;
        __syncthreads();
        shm[t] += tv;
        __syncthreads();
    }
    int run = row * N + shm[t] - s;   // global exclusive prefix
    h[base + 0] = run;             run += v0;
    h[base + 1] = run;             run += v1;
    h[base + 2] = run;             run += v2;
    h[base + 3] = run;
}

// ---------------- scatter into buckets (4 elements / thread) ----------------
__global__ void scatter_kernel(const float4* __restrict__ sims4, int M, int N) {
    int i4 = blockIdx.x * blockDim.x + threadIdx.x;
    int total4 = (M * N) >> 2;              // N % 4 == 0
    if (i4 >= total4) return;
    int i = i4 * 4;
    int row = i / N;                        // all 4 in same row (N % 4 == 0)
    int col = i - row * N;
    float4 v = sims4[i4];
    int* h = g_hist + row * NB;
    float vv[4] = {v.x, v.y, v.z, v.w};
#pragma unroll
    for (int e = 0; e < 4; e++) {
        int pos = atomicAdd(&h[sortable(vv[e]) >> 20], 1);
        g_pair[pos] = make_int2(__float_as_int(vv[e]), col + e);
    }
}

// ---------------- parallel PAV (nonincreasing isotonic regression) ----------
__global__ void pav_kernel(float* __restrict__ ranks, int M, int N) {
    int row = blockIdx.x;
    const int2* pair = g_pair + (size_t)row * N;
    double* csum = g_csum + (size_t)row * N;
    int*    ccnt = g_ccnt + (size_t)row * N;
    double* ssum = g_ssum + (size_t)row * N;
    int*    scnt = g_scnt + (size_t)row * N;
    int*    sbnd = g_sbnd + (size_t)row * N;

    int t = threadIdx.x;
    int L = (N + PAV_TPB - 1) / PAV_TPB;
    int j0 = min(t * L, N);
    int j1 = min(j0 + L, N);

    __shared__ int    snb[PAV_TPB];
    __shared__ double s1sum[PAV_TPB];
    __shared__ int    s1cnt[PAV_TPB];
    __shared__ int    sP;

    // --- phase 1: chunk PAV with register-cached stack top ---
    double lsum[LMAX];
    int    lcnt[LMAX];
    double topS = 0.0;
    int    topC = 0;
    int p = 0;
    for (int j = j0; j < j1; j++) {
        float v = __int_as_float(pair[j].x);
        double cs = -10.0 * (double)v - (double)(N - j);   // y_j = s_j - (n - j)
        int cc = 1;
        while (p > 0 && topS * (double)cc < cs * (double)topC) {
            cs += topS; cc += topC; p--;
            if (p > 0) { topS = lsum[p - 1]; topC = lcnt[p - 1]; }
        }
        if (p > 0) { lsum[p - 1] = topS; lcnt[p - 1] = topC; }
        topS = cs; topC = cc; p++;
    }
    if (p > 0) { lsum[p - 1] = topS; lcnt[p - 1] = topC; }
    for (int b = 0; b < p; b++) { csum[j0 + b] = lsum[b]; ccnt[j0 + b] = lcnt[b]; }
    snb[t] = p;
    if (p >= 1) { s1sum[t] = lsum[0]; s1cnt[t] = lcnt[0]; }
    __syncthreads();

    // --- phase 2: sequential merge of chunk block lists ---
    if (t == 0) {
        int P = 0;
        double TS = 0.0; int TC = 0;
        for (int tt = 0; tt < PAV_TPB; tt++) {
            int nb = snb[tt];
            int bbase = tt * L;
            for (int b = 0; b < nb; b++) {
                double cs; int cc;
                if (b == 0) { cs = s1sum[tt]; cc = s1cnt[tt]; }
                else        { cs = csum[bbase + b]; cc = ccnt[bbase + b]; }
                while (P > 0 && TS * (double)cc < cs * (double)TC) {
                    cs += TS; cc += TC; P--;
                    if (P > 0) { TS = ssum[P - 1]; TC = scnt[P - 1]; }
                }
                if (P > 0) { ssum[P - 1] = TS; scnt[P - 1] = TC; }
                TS = cs; TC = cc; P++;
            }
        }
        if (P > 0) { ssum[P - 1] = TS; scnt[P - 1] = TC; }
        int acc = 0;
        for (int b = 0; b < P; b++) { acc += scnt[b]; sbnd[b] = acc; }
        sP = P;
    }
    __syncthreads();

    // --- phase 3: per-element dual lookup + scatter primal ---
    int P = sP;
    for (int j = t; j < N; j += PAV_TPB) {
        int2 pr = pair[j];
        int lo = 0, hi = P - 1;
        while (lo < hi) {
            int mid = (lo + hi) >> 1;
            if (sbnd[mid] > j) hi = mid; else lo = mid + 1;
        }
        double dual = ssum[lo] / (double)scnt[lo];
        double s = -10.0 * (double)__int_as_float(pr.x);
        ranks[(size_t)row * N + pr.y] = (float)(s - dual);
    }
}

// ---------------- host launch ----------------
extern "C" void kernel_launch(void* const* d_in, const int* in_sizes, int n_in,
                              void* d_out, int out_size) {
    const float* q      = (const float*)d_in[0];
    const float* corpus = (const float*)d_in[1];
    int M = in_sizes[0] / DIM;   // 16
    int N = in_sizes[1] / DIM;   // 50000
    if (M > MAXM) M = MAXM;
    if (N > MAXN) N = MAXN;

    float* sims  = (float*)d_out;
    float* ranks = sims + (size_t)M * N;

    void* p_hist;
    cudaGetSymbolAddress(&p_hist, g_hist);
    cudaMemsetAsync(p_hist, 0, (size_t)M * NB * sizeof(int));

    qnorm_kernel<<<M, 128>>>(q, M);

    static int smem_set = 0;
    if (!smem_set) {
        cudaFuncSetAttribute(sim_kernel,
                             cudaFuncAttributeMaxDynamicSharedMemorySize, SMEM_DYN);
        smem_set = 1;
    }
    sim_kernel<<<SIM_BLOCKS, SIM_TPB, SMEM_DYN>>>(
        (const float4*)corpus, sims, M, N);

    scan_kernel<<<M, 1024>>>(N);

    int total4 = (M * N) / 4;
    scatter_kernel<<<(total4 + 255) / 256, 256>>>((const float4*)sims, M, N);

    pav_kernel<<<M, PAV_TPB>>>(ranks, M, N);
}

// round 5
// speedup vs baseline: 5.9167x; 3.5926x over previous
#include <cuda_runtime.h>
#include <cstdint>

#define DIM   384
#define DIM4  (DIM / 4)
#define MAXM  16
#define MAXN  50000
#define NB    4096                 // buckets per row (top 12 bits of sortable key)
#define BSHIFT 20                  // 32 - 12
#define FXS   1099511627776.0      // 2^40 fixed-point scale

#define TILE_DOCS 32
#define TILE_F4   (TILE_DOCS * DIM4)     // 3072 float4 = 48 KB
#define SIM_TPB   256
#define SIM_BLOCKS 148
#define LD_PER_THR (TILE_F4 / SIM_TPB)   // 12
#define DPW 4
#define SMEM_DYN ((MAXM * DIM4 + 2 * TILE_F4) * (int)sizeof(float4))   // 120 KB

#define PAVB_TPB 256
#define BPT (NB / PAVB_TPB)              // 16 buckets per thread
#define PAVB_SMEM (NB * (int)(sizeof(double) + 2 * sizeof(int)))      // 64 KB

// ---- static device scratch (no allocations allowed) ----
__device__ float              g_qn[MAXM * DIM];
__device__ int                g_cnt[MAXM * NB];
__device__ unsigned long long g_sum[MAXM * NB];   // int64 fixed-point sum of sims
__device__ double             g_dual[MAXM * NB];  // per-bucket PAV dual

__device__ __forceinline__ unsigned sortable(float f) {
    unsigned u = __float_as_uint(f);
    return (u & 0x80000000u) ? ~u : (u | 0x80000000u);   // ascending order
}

// ---- cp.async helpers ----
__device__ __forceinline__ void cp16(void* smem, const void* gmem) {
    unsigned s = (unsigned)__cvta_generic_to_shared(smem);
    asm volatile("cp.async.cg.shared.global [%0], [%1], 16;\n"
                 :: "r"(s), "l"(gmem) : "memory");
}
__device__ __forceinline__ void cp_commit() {
    asm volatile("cp.async.commit_group;\n" ::: "memory");
}
template <int W>
__device__ __forceinline__ void cp_wait() {
    asm volatile("cp.async.wait_group %0;\n" :: "n"(W) : "memory");
}

// ---------------- query normalization (launch #1) ----------------
__global__ void qnorm_kernel(const float* __restrict__ q, int M) {
    int row = blockIdx.x;
    float ss = 0.f;
    for (int i = threadIdx.x; i < DIM; i += blockDim.x) {
        float v = q[row * DIM + i];
        ss += v * v;
    }
    __shared__ float red[128];
    red[threadIdx.x] = ss;
    __syncthreads();
    for (int s = 64; s > 0; s >>= 1) {
        if (threadIdx.x < s) red[threadIdx.x] += red[threadIdx.x + s];
        __syncthreads();
    }
    float inv = 1.f / fmaxf(sqrtf(red[0]), 1e-12f);
    for (int i = threadIdx.x; i < DIM; i += blockDim.x)
        g_qn[row * DIM + i] = q[row * DIM + i] * inv;
}

// ---------------- zero-fill (launches #2, #3 — also position sim at #4) ----
__global__ void zero_cnt_kernel() {
    int i = blockIdx.x * blockDim.x + threadIdx.x;
    if (i < MAXM * NB) g_cnt[i] = 0;
}
__global__ void zero_sum_kernel() {
    int i = blockIdx.x * blockDim.x + threadIdx.x;
    if (i < MAXM * NB) g_sum[i] = 0ull;
}

// ---------------- cosine similarity GEMM (launch #4) ------------------------
__device__ __forceinline__ void sim_prefetch(float4* dst, const float4* __restrict__ corpus4,
                                             int tile, int N) {
    int docbase = tile * TILE_DOCS;
#pragma unroll
    for (int j = 0; j < LD_PER_THR; j++) {
        int idx = threadIdx.x + j * SIM_TPB;
        int d = idx / DIM4;
        int c = idx - d * DIM4;
        int doc = docbase + d;
        if (doc < N) cp16(dst + idx, corpus4 + (size_t)doc * DIM4 + c);
    }
}

extern __shared__ float4 sh4[];   // [0,1536): queries, then 2 x 3072 tile buffers

__global__ void __launch_bounds__(SIM_TPB, 1)
sim_kernel(const float4* __restrict__ corpus4, float* __restrict__ sims,
           int M, int N) {
    float4* qs    = sh4;
    float4* tiles = sh4 + MAXM * DIM4;

    for (int i = threadIdx.x; i < MAXM * DIM4; i += SIM_TPB)
        qs[i] = ((const float4*)g_qn)[i];

    int ntiles = (N + TILE_DOCS - 1) / TILE_DOCS;
    int t0 = blockIdx.x;
    if (t0 < ntiles) sim_prefetch(tiles, corpus4, t0, N);
    cp_commit();

    int warp = threadIdx.x >> 5, lane = threadIdx.x & 31;
    __shared__ float st[8 * DPW * 16];

    int it = 0;
    for (int t = t0; t < ntiles; t += gridDim.x, it++) {
        float4* cur = tiles + (it & 1) * TILE_F4;
        float4* nxt = tiles + ((it + 1) & 1) * TILE_F4;
        int tn = t + gridDim.x;
        if (tn < ntiles) {
            sim_prefetch(nxt, corpus4, tn, N);
            cp_commit();
            cp_wait<1>();
        } else {
            cp_wait<0>();
        }
        __syncthreads();

        // ---- compute 32 docs x 16 queries from SMEM ----
        const float4* vbase = cur + warp * DPW * DIM4;
        float acc[DPW][16];
        float ss[DPW];
#pragma unroll
        for (int d = 0; d < DPW; d++) {
            ss[d] = 0.f;
#pragma unroll
            for (int q = 0; q < 16; q++) acc[d][q] = 0.f;
        }
#pragma unroll
        for (int itk = 0; itk < 3; itk++) {
            int k = lane + itk * 32;
            float4 v[DPW];
#pragma unroll
            for (int d = 0; d < DPW; d++) {
                v[d] = vbase[d * DIM4 + k];
                ss[d] += v[d].x * v[d].x + v[d].y * v[d].y +
                         v[d].z * v[d].z + v[d].w * v[d].w;
            }
#pragma unroll
            for (int q = 0; q < 16; q++) {
                float4 qq = qs[q * DIM4 + k];
#pragma unroll
                for (int d = 0; d < DPW; d++) {
                    acc[d][q] += qq.x * v[d].x + qq.y * v[d].y +
                                 qq.z * v[d].z + qq.w * v[d].w;
                }
            }
        }
#pragma unroll
        for (int off = 16; off; off >>= 1) {
#pragma unroll
            for (int d = 0; d < DPW; d++) {
                ss[d] += __shfl_xor_sync(0xffffffffu, ss[d], off);
#pragma unroll
                for (int q = 0; q < 16; q++)
                    acc[d][q] += __shfl_xor_sync(0xffffffffu, acc[d][q], off);
            }
        }
        if (lane == 0) {
#pragma unroll
            for (int d = 0; d < DPW; d++) {
                float inv = 1.f / fmaxf(sqrtf(ss[d]), 1e-12f);
#pragma unroll
                for (int q = 0; q < 16; q++)
                    st[(warp * DPW + d) * 16 + q] = acc[d][q] * inv;
            }
        }
        __syncthreads();

        // epilogue: write sims + bucket count & fixed-point sum atomics
        int docbase = t * TILE_DOCS;
        for (int i = threadIdx.x; i < TILE_DOCS * M; i += SIM_TPB) {
            int q = i / TILE_DOCS;
            int w = i - q * TILE_DOCS;
            int doc = docbase + w;
            if (doc < N) {
                float v = st[w * 16 + q];
                sims[(size_t)q * N + doc] = v;
                unsigned b = sortable(v) >> BSHIFT;
                atomicAdd(&g_cnt[q * NB + b], 1);
                long long fx = __double2ll_rn((double)v * FXS);
                atomicAdd(&g_sum[q * NB + b], (unsigned long long)fx);
            }
        }
        __syncthreads();   // epilogue done before buffer reuse
    }
}

// ---------------- bucket-level PAV, fully in SMEM (launch #5) ---------------
// One block per row. Buckets are atomic groups: y-sum per bucket is computed
// from (count, sum) + positions; PAV merges groups; per-bucket dual emitted.
__global__ void pavB_kernel(int N) {
    int row = blockIdx.x;
    int t = threadIdx.x;
    extern __shared__ char sm[];
    double* ysum = (double*)sm;            // NB doubles: y-sums -> block sums (in place)
    int*    cnt  = (int*)(ysum + NB);      // NB ints:    counts -> block counts
    int*    bend = cnt + NB;               // NB ints:    block end-bucket (exclusive)
    __shared__ int    snb[PAVB_TPB];
    __shared__ int    sscan[PAVB_TPB];
    __shared__ int    sP;

    int base = t * BPT;

    // load counts + z-sums (z = -10 * v)
    int lc[BPT];
    int tsum = 0;
#pragma unroll
    for (int e = 0; e < BPT; e++) {
        int b = base + e;
        int c = g_cnt[row * NB + b];
        lc[e] = c;
        cnt[b] = c;
        long long s = (long long)g_sum[row * NB + b];
        ysum[b] = -10.0 * ((double)s / FXS);
        tsum += c;
    }
    sscan[t] = tsum;
    __syncthreads();
    for (int off = 1; off < PAVB_TPB; off <<= 1) {
        int tv = (t >= off) ? sscan[t - off] : 0;
        __syncthreads();
        sscan[t] += tv;
        __syncthreads();
    }
    int run = sscan[t] - tsum;   // exclusive position prefix within row

    // subtract w-part: sum_{j=P..P+c-1}(N - j) = c*N - c*P - c(c-1)/2
#pragma unroll
    for (int e = 0; e < BPT; e++) {
        int c = lc[e];
        if (c) {
            double P = (double)run;
            ysum[base + e] -= ((double)c * (double)N - (double)c * P
                               - (double)c * (double)(c - 1) * 0.5);
        }
        run += c;
    }
    __syncthreads();

    // phase 1: chunk PAV over this thread's BPT buckets (skip empties)
    double lsum[BPT];
    int    lcn[BPT];
    int    lend[BPT];
    int p = 0;
#pragma unroll
    for (int e = 0; e < BPT; e++) {
        int cc = lc[e];
        if (!cc) continue;
        double cs = ysum[base + e];
        while (p > 0 && lsum[p - 1] * (double)cc < cs * (double)lcn[p - 1]) {
            cs += lsum[p - 1]; cc += lcn[p - 1]; p--;
        }
        lsum[p] = cs; lcn[p] = cc; lend[p] = base + e + 1; p++;
    }
    for (int k = 0; k < p; k++) {
        ysum[base + k] = lsum[k]; cnt[base + k] = lcn[k]; bend[base + k] = lend[k];
    }
    snb[t] = p;
    __syncthreads();

    // phase 2: thread-0 stack merge of chunk lists (in place; write idx <= read idx)
    if (t == 0) {
        int P = 0;
        for (int tt = 0; tt < PAVB_TPB; tt++) {
            int nb = snb[tt];
            int bb = tt * BPT;
            for (int k = 0; k < nb; k++) {
                double cs = ysum[bb + k];
                int cc = cnt[bb + k];
                int en = bend[bb + k];
                while (P > 0 && ysum[P - 1] * (double)cc < cs * (double)cnt[P - 1]) {
                    cs += ysum[P - 1]; cc += cnt[P - 1]; P--;
                }
                ysum[P] = cs; cnt[P] = cc; bend[P] = en; P++;
            }
        }
        sP = P;
    }
    __syncthreads();

    // phase 3: per-bucket dual via binary search over block end-buckets
    int P = sP;
    for (int b = t; b < NB; b += PAVB_TPB) {
        int lo = 0, hi = P - 1;
        while (lo < hi) {
            int mid = (lo + hi) >> 1;
            if (bend[mid] > b) hi = mid; else lo = mid + 1;
        }
        g_dual[row * NB + b] = ysum[lo] / (double)cnt[lo];
    }
}

// ---------------- rank output, fully coalesced (launch #6) ------------------
__global__ void output_kernel(const float4* __restrict__ sims4,
                              float4* __restrict__ ranks4, int M, int N) {
    int i4 = blockIdx.x * blockDim.x + threadIdx.x;
    int total4 = (M * N) >> 2;     // N % 4 == 0
    if (i4 >= total4) return;
    int i = i4 * 4;
    int row = i / N;
    float4 v = sims4[i4];
    const double* dr = g_dual + row * NB;
    float4 o;
    o.x = (float)(-10.0 * (double)v.x - dr[sortable(v.x) >> BSHIFT]);
    o.y = (float)(-10.0 * (double)v.y - dr[sortable(v.y) >> BSHIFT]);
    o.z = (float)(-10.0 * (double)v.z - dr[sortable(v.z) >> BSHIFT]);
    o.w = (float)(-10.0 * (double)v.w - dr[sortable(v.w) >> BSHIFT]);
    ranks4[i4] = o;
}

// ---------------- host launch ----------------
extern "C" void kernel_launch(void* const* d_in, const int* in_sizes, int n_in,
                              void* d_out, int out_size) {
    const float* q      = (const float*)d_in[0];
    const float* corpus = (const float*)d_in[1];
    int M = in_sizes[0] / DIM;   // 16
    int N = in_sizes[1] / DIM;   // 50000
    if (M > MAXM) M = MAXM;
    if (N > MAXN) N = MAXN;

    float* sims  = (float*)d_out;
    float* ranks = sims + (size_t)M * N;

    static int smem_set = 0;
    if (!smem_set) {
        cudaFuncSetAttribute(sim_kernel,
                             cudaFuncAttributeMaxDynamicSharedMemorySize, SMEM_DYN);
        cudaFuncSetAttribute(pavB_kernel,
                             cudaFuncAttributeMaxDynamicSharedMemorySize, PAVB_SMEM);
        smem_set = 1;
    }

    qnorm_kernel<<<M, 128>>>(q, M);                              // launch 1
    zero_cnt_kernel<<<(MAXM * NB) / 256, 256>>>();               // launch 2
    zero_sum_kernel<<<(MAXM * NB) / 256, 256>>>();               // launch 3
    sim_kernel<<<SIM_BLOCKS, SIM_TPB, SMEM_DYN>>>(               // launch 4 (profiled)
        (const float4*)corpus, sims, M, N);
    pavB_kernel<<<M, PAVB_TPB, PAVB_SMEM>>>(N);                  // launch 5
    int total4 = (M * N) / 4;
    output_kernel<<<(total4 + 255) / 256, 256>>>(                // launch 6
        (const float4*)sims, (float4*)ranks, M, N);
}

// round 8
// speedup vs baseline: 7.2012x; 1.2171x over previous
#include <cuda_runtime.h>
#include <cstdint>

#define DIM   384
#define DIM4  (DIM / 4)
#define MAXM  16
#define MAXN  50000
#define NB    4096                 // buckets per row (top 12 bits of sortable key)
#define BSHIFT 20                  // 32 - 12
#define FXS   1099511627776.0      // 2^40 fixed-point scale

// ---- sim kernel geometry ----
#define TILE_DOCS 48
#define ROWP      388              // padded row stride in floats (bank-conflict-free)
#define ROWP4     97               // in float4
#define SIM_TPB   256
#define SIM_BLOCKS 148
// SMEM float offsets
#define QS_F      (2 * 16 * ROWP)                 // 12416 floats: [hl][q][k]
#define TILE_F    (TILE_DOCS * ROWP)              // 18624 floats per buffer
#define OFF_TILES QS_F
#define OFF_PART  (QS_F + 2 * TILE_F)             // 49664
#define PART_F    (2 * TILE_DOCS * 17)            // padded [half][d][q], stride 17
#define OFF_INV   (OFF_PART + PART_F)
#define SMEM_FLOATS (OFF_INV + TILE_DOCS)
#define SMEM_DYN  (SMEM_FLOATS * (int)sizeof(float))   // ~205 KB

#define PAVB_TPB 256
#define BPT (NB / PAVB_TPB)              // 16 buckets per thread
#define PAVB_SMEM (NB * (int)(sizeof(double) + 2 * sizeof(int)))      // 64 KB

// ---- static device scratch (no allocations allowed) ----
__device__ float              g_qhi[16 * DIM];
__device__ float              g_qlo[16 * DIM];
__device__ int                g_cnt[MAXM * NB];
__device__ unsigned long long g_sum[MAXM * NB];
__device__ double             g_dual[MAXM * NB];

__device__ __forceinline__ unsigned sortable(float f) {
    unsigned u = __float_as_uint(f);
    return (u & 0x80000000u) ? ~u : (u | 0x80000000u);   // ascending order
}

__device__ __forceinline__ unsigned to_tf32(float v) {
    unsigned r;
    asm("cvt.rna.tf32.f32 %0, %1;" : "=r"(r) : "f"(v));
    return r;
}

__device__ __forceinline__ void mma_tf32(float c[4], unsigned a0, unsigned a1,
                                         unsigned a2, unsigned a3,
                                         unsigned b0, unsigned b1) {
    asm volatile(
        "mma.sync.aligned.m16n8k8.row.col.f32.tf32.tf32.f32 "
        "{%0,%1,%2,%3},{%4,%5,%6,%7},{%8,%9},{%0,%1,%2,%3};"
        : "+f"(c[0]), "+f"(c[1]), "+f"(c[2]), "+f"(c[3])
        : "r"(a0), "r"(a1), "r"(a2), "r"(a3), "r"(b0), "r"(b1));
}

// ---- cp.async helpers ----
__device__ __forceinline__ void cp16(void* smem, const void* gmem) {
    unsigned s = (unsigned)__cvta_generic_to_shared(smem);
    asm volatile("cp.async.cg.shared.global [%0], [%1], 16;\n"
                 :: "r"(s), "l"(gmem) : "memory");
}
__device__ __forceinline__ void cp_commit() {
    asm volatile("cp.async.commit_group;\n" ::: "memory");
}
template <int W>
__device__ __forceinline__ void cp_wait() {
    asm volatile("cp.async.wait_group %0;\n" :: "n"(W) : "memory");
}

// ---------------- launch 1: query normalize + tf32 split + zero counters ----
__global__ void prep_kernel(const float* __restrict__ q, int M) {
    if (blockIdx.x < 16) {
        int row = blockIdx.x;
        if (row >= M) return;
        float ss = 0.f;
        for (int i = threadIdx.x; i < DIM; i += blockDim.x) {
            float v = q[row * DIM + i];
            ss += v * v;
        }
        __shared__ float red[256];
        red[threadIdx.x] = ss;
        __syncthreads();
        for (int s = 128; s > 0; s >>= 1) {
            if (threadIdx.x < s) red[threadIdx.x] += red[threadIdx.x + s];
            __syncthreads();
        }
        float inv = 1.f / fmaxf(sqrtf(red[0]), 1e-12f);
        for (int i = threadIdx.x; i < DIM; i += blockDim.x) {
            float v = q[row * DIM + i] * inv;
            unsigned hb = to_tf32(v);
            float hv = __uint_as_float(hb);
            g_qhi[row * DIM + i] = hv;
            g_qlo[row * DIM + i] = __uint_as_float(to_tf32(v - hv));
        }
    } else {
        int b = blockIdx.x - 16;                 // 128 zero blocks
        int i = b * blockDim.x + threadIdx.x;    // 32768 threads
        g_cnt[i * 2 + 0] = 0;  g_cnt[i * 2 + 1] = 0;
        g_sum[i * 2 + 0] = 0ull; g_sum[i * 2 + 1] = 0ull;
    }
}

// ---------------- launch 2: sims via split-tf32 mma.sync --------------------
extern __shared__ float shf[];

__global__ void __launch_bounds__(SIM_TPB, 1)
sim_kernel(const float4* __restrict__ corpus4, float* __restrict__ sims,
           int M, int N) {
    float*  qs    = shf;                         // [hl][q][ROWP]
    float*  part  = shf + OFF_PART;              // [half][d][17]
    float*  invn  = shf + OFF_INV;               // [TILE_DOCS]

    // stage split queries (pad columns never read)
    for (int i = threadIdx.x; i < 16 * DIM; i += SIM_TPB) {
        int qq = i / DIM, k = i - qq * DIM;
        qs[qq * ROWP + k]              = g_qhi[i];
        qs[QS_F / 2 + qq * ROWP + k]   = g_qlo[i];
    }

    int ntiles = (N + TILE_DOCS - 1) / TILE_DOCS;
    int tid  = threadIdx.x;
    int wid  = tid >> 5, lane = tid & 31;
    int g    = lane >> 2, tl = lane & 3;

    // prefetch first tile
    {
        int docbase = blockIdx.x * TILE_DOCS;
        float4* dst = (float4*)(shf + OFF_TILES);
#pragma unroll
        for (int j = 0; j < 18; j++) {
            int idx = tid + j * SIM_TPB;         // 0..4607 = 48 docs * 96 f4
            int d = idx / 96, c = idx - d * 96;
            int doc = docbase + d;
            if (doc < N) cp16(dst + d * ROWP4 + c, corpus4 + (size_t)doc * 96 + c);
        }
    }
    cp_commit();

    int it = 0;
    for (int t = blockIdx.x; t < ntiles; t += gridDim.x, it++) {
        float* cur = shf + OFF_TILES + (it & 1) * TILE_F;
        float* nxt = shf + OFF_TILES + ((it + 1) & 1) * TILE_F;
        int tn = t + gridDim.x;
        if (tn < ntiles) {
            int docbase = tn * TILE_DOCS;
            float4* dst = (float4*)nxt;
#pragma unroll
            for (int j = 0; j < 18; j++) {
                int idx = tid + j * SIM_TPB;
                int d = idx / 96, c = idx - d * 96;
                int doc = docbase + d;
                if (doc < N) cp16(dst + d * ROWP4 + c, corpus4 + (size_t)doc * 96 + c);
            }
            cp_commit();
            cp_wait<1>();
        } else {
            cp_wait<0>();
        }
        __syncthreads();

        int docbase = t * TILE_DOCS;

        if (wid < 6) {
            // MMA warp: doc-group dg (16 docs), K-half h (192 floats)
            int dg = wid >> 1, h = wid & 1;
            const float* arow0 = cur + (dg * 16 + g) * ROWP;
            const float* arow8 = arow0 + 8 * ROWP;
            float c0[4] = {0.f, 0.f, 0.f, 0.f};   // queries 0-7
            float c1[4] = {0.f, 0.f, 0.f, 0.f};   // queries 8-15
            int k0 = h * 192;
#pragma unroll 4
            for (int s = 0; s < 24; s++) {
                int k = k0 + s * 8 + tl;
                float a0 = arow0[k],     a1 = arow8[k];
                float a2 = arow0[k + 4], a3 = arow8[k + 4];
                unsigned ah0 = to_tf32(a0), ah1 = to_tf32(a1);
                unsigned ah2 = to_tf32(a2), ah3 = to_tf32(a3);
                unsigned al0 = to_tf32(a0 - __uint_as_float(ah0));
                unsigned al1 = to_tf32(a1 - __uint_as_float(ah1));
                unsigned al2 = to_tf32(a2 - __uint_as_float(ah2));
                unsigned al3 = to_tf32(a3 - __uint_as_float(ah3));
                // B fragments (already tf32-valued in SMEM)
                const float* qh0 = qs + g * ROWP + k;              // q = g
                const float* qh1 = qs + (8 + g) * ROWP + k;        // q = 8+g
                const float* ql0 = qs + QS_F / 2 + g * ROWP + k;
                const float* ql1 = qs + QS_F / 2 + (8 + g) * ROWP + k;
                unsigned bh00 = __float_as_uint(qh0[0]);
                unsigned bh01 = __float_as_uint(qh0[4]);
                unsigned bh10 = __float_as_uint(qh1[0]);
                unsigned bh11 = __float_as_uint(qh1[4]);
                unsigned bl00 = __float_as_uint(ql0[0]);
                unsigned bl01 = __float_as_uint(ql0[4]);
                unsigned bl10 = __float_as_uint(ql1[0]);
                unsigned bl11 = __float_as_uint(ql1[4]);
                mma_tf32(c0, ah0, ah1, ah2, ah3, bh00, bh01);
                mma_tf32(c0, ah0, ah1, ah2, ah3, bl00, bl01);
                mma_tf32(c0, al0, al1, al2, al3, bh00, bh01);
                mma_tf32(c1, ah0, ah1, ah2, ah3, bh10, bh11);
                mma_tf32(c1, ah0, ah1, ah2, ah3, bl10, bl11);
                mma_tf32(c1, al0, al1, al2, al3, bh10, bh11);
            }
            // write partials: part[h][d][q], stride 17
            float* pb = part + h * (TILE_DOCS * 17);
            int d0 = dg * 16 + g;
            pb[d0 * 17 + tl * 2]           = c0[0];
            pb[d0 * 17 + tl * 2 + 1]       = c0[1];
            pb[(d0 + 8) * 17 + tl * 2]     = c0[2];
            pb[(d0 + 8) * 17 + tl * 2 + 1] = c0[3];
            pb[d0 * 17 + 8 + tl * 2]           = c1[0];
            pb[d0 * 17 + 8 + tl * 2 + 1]       = c1[1];
            pb[(d0 + 8) * 17 + 8 + tl * 2]     = c1[2];
            pb[(d0 + 8) * 17 + 8 + tl * 2 + 1] = c1[3];
        } else {
            // norm warps: lanes of warps 6,7 -> one doc each
            int d = (wid - 6) * 32 + lane;
            if (d < TILE_DOCS) {
                const float4* r4 = (const float4*)(cur + d * ROWP);
                float ss = 0.f;
#pragma unroll 8
                for (int i = 0; i < 96; i++) {
                    float4 v = r4[i];
                    ss += v.x * v.x + v.y * v.y + v.z * v.z + v.w * v.w;
                }
                invn[d] = 1.f / fmaxf(sqrtf(ss), 1e-12f);
            }
        }
        __syncthreads();

        // epilogue: 768 outputs, thread -> (q = i/48, d = i%48)
        for (int i = tid; i < TILE_DOCS * 16; i += SIM_TPB) {
            int qq = i / TILE_DOCS;
            int d  = i - qq * TILE_DOCS;
            int doc = docbase + d;
            if (doc < N && qq < M) {
                float v = (part[d * 17 + qq] + part[TILE_DOCS * 17 + d * 17 + qq])
                          * invn[d];
                sims[(size_t)qq * N + doc] = v;
                unsigned b = sortable(v) >> BSHIFT;
                atomicAdd(&g_cnt[qq * NB + b], 1);
                long long fx = __double2ll_rn((double)v * FXS);
                atomicAdd(&g_sum[qq * NB + b], (unsigned long long)fx);
            }
        }
        __syncthreads();   // before buffer reuse
    }
}

// ---------------- launch 3: bucket-level PAV in SMEM ------------------------
__global__ void pavB_kernel(int N) {
    int row = blockIdx.x;
    int t = threadIdx.x;
    extern __shared__ char sm[];
    double* ysum = (double*)sm;
    int*    cnt  = (int*)(ysum + NB);
    int*    bend = cnt + NB;
    __shared__ int snb[PAVB_TPB];
    __shared__ int sscan[PAVB_TPB];
    __shared__ int sP;

    int base = t * BPT;
    int lc[BPT];
    int tsum = 0;
#pragma unroll
    for (int e = 0; e < BPT; e++) {
        int b = base + e;
        int c = g_cnt[row * NB + b];
        lc[e] = c;
        cnt[b] = c;
        long long s = (long long)g_sum[row * NB + b];
        ysum[b] = -10.0 * ((double)s / FXS);
        tsum += c;
    }
    sscan[t] = tsum;
    __syncthreads();
    for (int off = 1; off < PAVB_TPB; off <<= 1) {
        int tv = (t >= off) ? sscan[t - off] : 0;
        __syncthreads();
        sscan[t] += tv;
        __syncthreads();
    }
    int run = sscan[t] - tsum;
#pragma unroll
    for (int e = 0; e < BPT; e++) {
        int c = lc[e];
        if (c) {
            double P = (double)run;
            ysum[base + e] -= ((double)c * (double)N - (double)c * P
                               - (double)c * (double)(c - 1) * 0.5);
        }
        run += c;
    }
    __syncthreads();

    double lsum[BPT];
    int    lcn[BPT];
    int    lend[BPT];
    int p = 0;
#pragma unroll
    for (int e = 0; e < BPT; e++) {
        int cc = lc[e];
        if (!cc) continue;
        double cs = ysum[base + e];
        while (p > 0 && lsum[p - 1] * (double)cc < cs * (double)lcn[p - 1]) {
            cs += lsum[p - 1]; cc += lcn[p - 1]; p--;
        }
        lsum[p] = cs; lcn[p] = cc; lend[p] = base + e + 1; p++;
    }
    for (int k = 0; k < p; k++) {
        ysum[base + k] = lsum[k]; cnt[base + k] = lcn[k]; bend[base + k] = lend[k];
    }
    snb[t] = p;
    __syncthreads();

    if (t == 0) {
        int P = 0;
        for (int tt = 0; tt < PAVB_TPB; tt++) {
            int nb = snb[tt];
            int bb = tt * BPT;
            for (int k = 0; k < nb; k++) {
                double cs = ysum[bb + k];
                int cc = cnt[bb + k];
                int en = bend[bb + k];
                while (P > 0 && ysum[P - 1] * (double)cc < cs * (double)cnt[P - 1]) {
                    cs += ysum[P - 1]; cc += cnt[P - 1]; P--;
                }
                ysum[P] = cs; cnt[P] = cc; bend[P] = en; P++;
            }
        }
        sP = P;
    }
    __syncthreads();

    int P = sP;
    for (int b = t; b < NB; b += PAVB_TPB) {
        int lo = 0, hi = P - 1;
        while (lo < hi) {
            int mid = (lo + hi) >> 1;
            if (bend[mid] > b) hi = mid; else lo = mid + 1;
        }
        g_dual[row * NB + b] = ysum[lo] / (double)cnt[lo];
    }
}

// ---------------- launch 4: rank output -------------------------------------
__global__ void output_kernel(const float4* __restrict__ sims4,
                              float4* __restrict__ ranks4, int M, int N) {
    int i4 = blockIdx.x * blockDim.x + threadIdx.x;
    int total4 = (M * N) >> 2;
    if (i4 >= total4) return;
    int i = i4 * 4;
    int row = i / N;
    float4 v = sims4[i4];
    const double* dr = g_dual + row * NB;
    float4 o;
    o.x = (float)(-10.0 * (double)v.x - dr[sortable(v.x) >> BSHIFT]);
    o.y = (float)(-10.0 * (double)v.y - dr[sortable(v.y) >> BSHIFT]);
    o.z = (float)(-10.0 * (double)v.z - dr[sortable(v.z) >> BSHIFT]);
    o.w = (float)(-10.0 * (double)v.w - dr[sortable(v.w) >> BSHIFT]);
    ranks4[i4] = o;
}

// ---------------- host launch ----------------
extern "C" void kernel_launch(void* const* d_in, const int* in_sizes, int n_in,
                              void* d_out, int out_size) {
    const float* q      = (const float*)d_in[0];
    const float* corpus = (const float*)d_in[1];
    int M = in_sizes[0] / DIM;   // 16
    int N = in_sizes[1] / DIM;   // 50000
    if (M > MAXM) M = MAXM;
    if (N > MAXN) N = MAXN;

    float* sims  = (float*)d_out;
    float* ranks = sims + (size_t)M * N;

    cudaFuncSetAttribute(sim_kernel,
                         cudaFuncAttributeMaxDynamicSharedMemorySize, SMEM_DYN);
    cudaFuncSetAttribute(pavB_kernel,
                         cudaFuncAttributeMaxDynamicSharedMemorySize, PAVB_SMEM);

    prep_kernel<<<16 + 128, 256>>>(q, M);                        // launch 1
    sim_kernel<<<SIM_BLOCKS, SIM_TPB, SMEM_DYN>>>(               // launch 2
        (const float4*)corpus, sims, M, N);
    pavB_kernel<<<M, PAVB_TPB, PAVB_SMEM>>>(N);                  // launch 3
    int total4 = (M * N) / 4;
    output_kernel<<<(total4 + 255) / 256, 256>>>(                // launch 4
        (const float4*)sims, (float4*)ranks, M, N);
}

// round 9
// speedup vs baseline: 8.8750x; 1.2324x over previous
#include <cuda_runtime.h>
#include <cstdint>

#define DIM   384
#define MAXM  16
#define MAXN  50000
#define NB    4096                 // buckets per row (top 12 bits of sortable key)
#define BSHIFT 20                  // 32 - 12
#define FXS   1099511627776.0      // 2^40 fixed-point scale

// ---- sim kernel geometry ----
#define TILE_DOCS 48
#define ROWP      388              // padded corpus row stride in floats
#define ROWP4     97               // in float4
#define SIM_TPB   256
#define SIM_BLOCKS 148
// SMEM float offsets: [bfragA 768 u4][bfragB 768 u4][2x tile][part][invn]
#define BFRAG_U4  (2 * 12 * 32)                   // 768 uint4 per table
#define OFF_TA    0                               // floats
#define OFF_TB    (BFRAG_U4 * 4)                  // 3072
#define OFF_TILES (2 * BFRAG_U4 * 4)              // 6144
#define TILE_F    (TILE_DOCS * ROWP)              // 18624
#define OFF_PART  (OFF_TILES + 2 * TILE_F)        // 43392
#define PART_F    (2 * TILE_DOCS * 17)            // 1632
#define OFF_INV   (OFF_PART + PART_F)
#define SMEM_FLOATS (OFF_INV + TILE_DOCS)
#define SMEM_DYN  (SMEM_FLOATS * (int)sizeof(float))   // ~180 KB

#define PAVB_TPB 256
#define BPT (NB / PAVB_TPB)              // 16 buckets per thread
#define PAVB_SMEM (NB * (int)(sizeof(double) + 2 * sizeof(int)))   // 64 KB

// ---- static device scratch (no allocations allowed) ----
__device__ float              g_qn[MAXM * DIM];
__device__ uint4              g_bfA[BFRAG_U4];   // group0 (queries 0-7) fragments
__device__ uint4              g_bfB[BFRAG_U4];   // group1 (queries 8-15)
__device__ int                g_cnt[MAXM * NB];
__device__ unsigned long long g_sum[MAXM * NB];
__device__ float              g_dualf[MAXM * NB];

__device__ __forceinline__ unsigned sortable(float f) {
    unsigned u = __float_as_uint(f);
    return (u & 0x80000000u) ? ~u : (u | 0x80000000u);   // ascending order
}

// pack two f32 -> bf16x2 (lo half = first arg, hi half = second arg)
__device__ __forceinline__ unsigned packbf(float lo, float hi) {
    unsigned r;
    asm("cvt.rn.bf16x2.f32 %0, %1, %2;" : "=r"(r) : "f"(hi), "f"(lo));
    return r;
}
__device__ __forceinline__ float bflo(unsigned u) { return __uint_as_float(u << 16); }
__device__ __forceinline__ float bfhi(unsigned u) { return __uint_as_float(u & 0xffff0000u); }

__device__ __forceinline__ void mma_bf16(float c[4], unsigned a0, unsigned a1,
                                         unsigned a2, unsigned a3,
                                         unsigned b0, unsigned b1) {
    asm volatile(
        "mma.sync.aligned.m16n8k16.row.col.f32.bf16.bf16.f32 "
        "{%0,%1,%2,%3},{%4,%5,%6,%7},{%8,%9},{%0,%1,%2,%3};"
        : "+f"(c[0]), "+f"(c[1]), "+f"(c[2]), "+f"(c[3])
        : "r"(a0), "r"(a1), "r"(a2), "r"(a3), "r"(b0), "r"(b1));
}

// ---- cp.async helpers ----
__device__ __forceinline__ void cp16(void* smem, const void* gmem) {
    unsigned s = (unsigned)__cvta_generic_to_shared(smem);
    asm volatile("cp.async.cg.shared.global [%0], [%1], 16;\n"
                 :: "r"(s), "l"(gmem) : "memory");
}
__device__ __forceinline__ void cp_commit() {
    asm volatile("cp.async.commit_group;\n" ::: "memory");
}
template <int W>
__device__ __forceinline__ void cp_wait() {
    asm volatile("cp.async.wait_group %0;\n" :: "n"(W) : "memory");
}

// ---------------- launch 1: zero counters ----------------
__global__ void zero_kernel() {
    int i = blockIdx.x * blockDim.x + threadIdx.x;   // 65536
    g_cnt[i] = 0;
    g_sum[i] = 0ull;
}

// ---------------- launch 2: query normalization ----------------
__global__ void qnorm_kernel(const float* __restrict__ q, int M) {
    int row = blockIdx.x;
    if (row >= M) return;
    float ss = 0.f;
    for (int i = threadIdx.x; i < DIM; i += blockDim.x) {
        float v = q[row * DIM + i];
        ss += v * v;
    }
    __shared__ float red[128];
    red[threadIdx.x] = ss;
    __syncthreads();
    for (int s = 64; s > 0; s >>= 1) {
        if (threadIdx.x < s) red[threadIdx.x] += red[threadIdx.x + s];
        __syncthreads();
    }
    float inv = 1.f / fmaxf(sqrtf(red[0]), 1e-12f);
    for (int i = threadIdx.x; i < DIM; i += blockDim.x)
        g_qn[row * DIM + i] = q[row * DIM + i] * inv;
}

// ---------------- launch 3: build B fragment tables (split-bf16) ------------
// One warp per (h, s). Fragment per lane: b0 = (k0+2tl, k0+2tl+1, col q),
// b1 = (k0+2tl+8, +9, col q). q = g (group0) / 8+g (group1).
__global__ void bfrag_kernel() {
    int hs = blockIdx.x;                 // 0..23
    int h = hs / 12, s = hs - h * 12;
    int lane = threadIdx.x;
    int g = lane >> 2, tl = lane & 3;
    int k0 = h * 192 + s * 16 + 2 * tl;
#pragma unroll
    for (int grp = 0; grp < 2; grp++) {
        const float* qp = g_qn + (grp * 8 + g) * DIM;
        float v00 = qp[k0],     v01 = qp[k0 + 1];
        float v10 = qp[k0 + 8], v11 = qp[k0 + 9];
        unsigned b0h = packbf(v00, v01);
        unsigned b1h = packbf(v10, v11);
        unsigned b0l = packbf(v00 - bflo(b0h), v01 - bfhi(b0h));
        unsigned b1l = packbf(v10 - bflo(b1h), v11 - bfhi(b1h));
        uint4 r = make_uint4(b0h, b1h, b0l, b1l);
        if (grp == 0) g_bfA[hs * 32 + lane] = r;
        else          g_bfB[hs * 32 + lane] = r;
    }
}

// ---------------- launch 4: sims via split-bf16 mma.sync --------------------
extern __shared__ float shf[];

__global__ void __launch_bounds__(SIM_TPB, 1)
sim_kernel(const float4* __restrict__ corpus4, float* __restrict__ sims,
           int M, int N) {
    uint4* tA    = (uint4*)(shf + OFF_TA);
    uint4* tB    = (uint4*)(shf + OFF_TB);
    float* part  = shf + OFF_PART;               // [half][d][17]
    float* invn  = shf + OFF_INV;                // [TILE_DOCS]

    // stage fragment tables
    for (int i = threadIdx.x; i < BFRAG_U4; i += SIM_TPB) {
        tA[i] = g_bfA[i];
        tB[i] = g_bfB[i];
    }

    int ntiles = (N + TILE_DOCS - 1) / TILE_DOCS;
    int tid  = threadIdx.x;
    int wid  = tid >> 5, lane = tid & 31;
    int g    = lane >> 2, tl = lane & 3;

    // prefetch first tile
    {
        int docbase = blockIdx.x * TILE_DOCS;
        float4* dst = (float4*)(shf + OFF_TILES);
#pragma unroll
        for (int j = 0; j < 18; j++) {
            int idx = tid + j * SIM_TPB;         // 48 docs * 96 f4
            int d = idx / 96, c = idx - d * 96;
            int doc = docbase + d;
            if (doc < N) cp16(dst + d * ROWP4 + c, corpus4 + (size_t)doc * 96 + c);
        }
    }
    cp_commit();

    int it = 0;
    for (int t = blockIdx.x; t < ntiles; t += gridDim.x, it++) {
        float* cur = shf + OFF_TILES + (it & 1) * TILE_F;
        float* nxt = shf + OFF_TILES + ((it + 1) & 1) * TILE_F;
        int tn = t + gridDim.x;
        if (tn < ntiles) {
            int docbase = tn * TILE_DOCS;
            float4* dst = (float4*)nxt;
#pragma unroll
            for (int j = 0; j < 18; j++) {
                int idx = tid + j * SIM_TPB;
                int d = idx / 96, c = idx - d * 96;
                int doc = docbase + d;
                if (doc < N) cp16(dst + d * ROWP4 + c, corpus4 + (size_t)doc * 96 + c);
            }
            cp_commit();
            cp_wait<1>();
        } else {
            cp_wait<0>();
        }
        __syncthreads();

        int docbase = t * TILE_DOCS;

        if (wid < 6) {
            // MMA warp: doc-group dg (16 docs), K-half h (192 floats, 12 k16 steps)
            int dg = wid >> 1, h = wid & 1;
            const float* arow0 = cur + (dg * 16 + g) * ROWP;
            const float* arow8 = arow0 + 8 * ROWP;
            const uint4* fA = tA + (h * 12) * 32 + lane;
            const uint4* fB = tB + (h * 12) * 32 + lane;
            float c0[4] = {0.f, 0.f, 0.f, 0.f};   // queries 0-7
            float c1[4] = {0.f, 0.f, 0.f, 0.f};   // queries 8-15
            int kbase = h * 192 + 2 * tl;
#pragma unroll
            for (int s = 0; s < 12; s++) {
                int k = kbase + s * 16;
                float2 va0 = *(const float2*)(arow0 + k);
                float2 va1 = *(const float2*)(arow8 + k);
                float2 vb0 = *(const float2*)(arow0 + k + 8);
                float2 vb1 = *(const float2*)(arow8 + k + 8);
                unsigned ah0 = packbf(va0.x, va0.y);
                unsigned ah1 = packbf(va1.x, va1.y);
                unsigned ah2 = packbf(vb0.x, vb0.y);
                unsigned ah3 = packbf(vb1.x, vb1.y);
                unsigned al0 = packbf(va0.x - bflo(ah0), va0.y - bfhi(ah0));
                unsigned al1 = packbf(va1.x - bflo(ah1), va1.y - bfhi(ah1));
                unsigned al2 = packbf(vb0.x - bflo(ah2), vb0.y - bfhi(ah2));
                unsigned al3 = packbf(vb1.x - bflo(ah3), vb1.y - bfhi(ah3));
                uint4 B0 = fA[s * 32];
                uint4 B1 = fB[s * 32];
                mma_bf16(c0, ah0, ah1, ah2, ah3, B0.x, B0.y);   // ah*bh
                mma_bf16(c0, ah0, ah1, ah2, ah3, B0.z, B0.w);   // ah*bl
                mma_bf16(c0, al0, al1, al2, al3, B0.x, B0.y);   // al*bh
                mma_bf16(c1, ah0, ah1, ah2, ah3, B1.x, B1.y);
                mma_bf16(c1, ah0, ah1, ah2, ah3, B1.z, B1.w);
                mma_bf16(c1, al0, al1, al2, al3, B1.x, B1.y);
            }
            // write partials: part[h][d][q], stride 17
            float* pb = part + h * (TILE_DOCS * 17);
            int d0 = dg * 16 + g;
            pb[d0 * 17 + tl * 2]           = c0[0];
            pb[d0 * 17 + tl * 2 + 1]       = c0[1];
            pb[(d0 + 8) * 17 + tl * 2]     = c0[2];
            pb[(d0 + 8) * 17 + tl * 2 + 1] = c0[3];
            pb[d0 * 17 + 8 + tl * 2]           = c1[0];
            pb[d0 * 17 + 8 + tl * 2 + 1]       = c1[1];
            pb[(d0 + 8) * 17 + 8 + tl * 2]     = c1[2];
            pb[(d0 + 8) * 17 + 8 + tl * 2 + 1] = c1[3];
        } else {
            // norm warps: one doc per lane (exact fp32 norms)
            int d = (wid - 6) * 32 + lane;
            if (d < TILE_DOCS) {
                const float4* r4 = (const float4*)(cur + d * ROWP);
                float ss = 0.f;
#pragma unroll 8
                for (int i = 0; i < 96; i++) {
                    float4 v = r4[i];
                    ss += v.x * v.x + v.y * v.y + v.z * v.z + v.w * v.w;
                }
                invn[d] = 1.f / fmaxf(sqrtf(ss), 1e-12f);
            }
        }
        __syncthreads();

        // epilogue: combine halves, write sims + bucket aggregates
        for (int i = tid; i < TILE_DOCS * 16; i += SIM_TPB) {
            int qq = i / TILE_DOCS;
            int d  = i - qq * TILE_DOCS;
            int doc = docbase + d;
            if (doc < N && qq < M) {
                float v = (part[d * 17 + qq] + part[TILE_DOCS * 17 + d * 17 + qq])
                          * invn[d];
                sims[(size_t)qq * N + doc] = v;
                unsigned b = sortable(v) >> BSHIFT;
                atomicAdd(&g_cnt[qq * NB + b], 1);
                long long fx = __double2ll_rn((double)v * FXS);
                atomicAdd(&g_sum[qq * NB + b], (unsigned long long)fx);
            }
        }
        __syncthreads();   // before buffer reuse
    }
}

// ---------------- launch 5: bucket-level PAV, hierarchical merge ------------
__global__ void pavB_kernel(int N) {
    int row = blockIdx.x;
    int t = threadIdx.x;
    int lane = t & 31, ww = t >> 5;     // 8 warps
    extern __shared__ char sm[];
    double* ysum = (double*)sm;          // NB
    int*    cnt  = (int*)(ysum + NB);    // NB
    int*    bend = cnt + NB;             // NB
    __shared__ int snb[PAVB_TPB];
    __shared__ int wnb[8];
    __shared__ int sscan[PAVB_TPB];
    __shared__ int sP;

    // A: coalesced load of counts + z-sums
    for (int b = t; b < NB; b += PAVB_TPB) {
        cnt[b] = g_cnt[row * NB + b];
        ysum[b] = -10.0 * ((double)(long long)g_sum[row * NB + b] / FXS);
    }
    __syncthreads();

    // B: per-chunk counts + block-wide exclusive scan of positions
    int base = t * BPT;
    int lc[BPT];
    int tsum = 0;
#pragma unroll
    for (int e = 0; e < BPT; e++) { lc[e] = cnt[base + e]; tsum += lc[e]; }
    sscan[t] = tsum;
    __syncthreads();
    for (int off = 1; off < PAVB_TPB; off <<= 1) {
        int tv = (t >= off) ? sscan[t - off] : 0;
        __syncthreads();
        sscan[t] += tv;
        __syncthreads();
    }
    int run = sscan[t] - tsum;
#pragma unroll
    for (int e = 0; e < BPT; e++) {
        int c = lc[e];
        if (c) {
            ysum[base + e] -= ((double)c * (double)N - (double)c * (double)run
                               - (double)c * (double)(c - 1) * 0.5);
        }
        run += c;
    }

    // C: per-thread chunk PAV (compacted in place into own chunk region)
    double lsum[BPT];
    int    lcn[BPT];
    int    lend[BPT];
    int p = 0;
#pragma unroll
    for (int e = 0; e < BPT; e++) {
        int cc = lc[e];
        if (!cc) continue;
        double cs = ysum[base + e];
        while (p > 0 && lsum[p - 1] * (double)cc < cs * (double)lcn[p - 1]) {
            cs += lsum[p - 1]; cc += lcn[p - 1]; p--;
        }
        lsum[p] = cs; lcn[p] = cc; lend[p] = base + e + 1; p++;
    }
    for (int k = 0; k < p; k++) {
        ysum[base + k] = lsum[k]; cnt[base + k] = lcn[k]; bend[base + k] = lend[k];
    }
    snb[t] = p;
    __syncthreads();

    // D: warp-leader merge of 32 chunk lists -> compacted at ww*512
    if (lane == 0) {
        int out = ww * 512;
        int P = 0;
        double TS = 0.0; int TC = 0, TE = 0;     // register-cached stack top
        for (int c = ww * 32; c < ww * 32 + 32; c++) {
            int nb = snb[c];
            int bb = c * BPT;
            for (int k = 0; k < nb; k++) {
                double cs = ysum[bb + k];
                int cc = cnt[bb + k];
                int en = bend[bb + k];
                while (P > 0 && TS * (double)cc < cs * (double)TC) {
                    cs += TS; cc += TC; P--;
                    if (P > 0) { TS = ysum[out + P - 1]; TC = cnt[out + P - 1]; TE = bend[out + P - 1]; }
                }
                if (P > 0) { ysum[out + P - 1] = TS; cnt[out + P - 1] = TC; bend[out + P - 1] = TE; }
                TS = cs; TC = cc; TE = en; P++;
            }
        }
        if (P > 0) { ysum[out + P - 1] = TS; cnt[out + P - 1] = TC; bend[out + P - 1] = TE; }
        wnb[ww] = P;
    }
    __syncthreads();

    // E: thread 0 merges 8 warp lists -> final compacted at 0
    if (t == 0) {
        int P = 0;
        double TS = 0.0; int TC = 0, TE = 0;
        for (int w2 = 0; w2 < 8; w2++) {
            int nb = wnb[w2];
            int bb = w2 * 512;
            for (int k = 0; k < nb; k++) {
                double cs = ysum[bb + k];
                int cc = cnt[bb + k];
                int en = bend[bb + k];
                while (P > 0 && TS * (double)cc < cs * (double)TC) {
                    cs += TS; cc += TC; P--;
                    if (P > 0) { TS = ysum[P - 1]; TC = cnt[P - 1]; TE = bend[P - 1]; }
                }
                if (P > 0) { ysum[P - 1] = TS; cnt[P - 1] = TC; bend[P - 1] = TE; }
                TS = cs; TC = cc; TE = en; P++;
            }
        }
        if (P > 0) { ysum[P - 1] = TS; cnt[P - 1] = TC; bend[P - 1] = TE; }
        sP = P;
    }
    __syncthreads();

    // F: per-bucket dual (float) via binary search over block end-buckets
    int P = sP;
    for (int b = t; b < NB; b += PAVB_TPB) {
        int lo = 0, hi = P - 1;
        while (lo < hi) {
            int mid = (lo + hi) >> 1;
            if (bend[mid] > b) hi = mid; else lo = mid + 1;
        }
        g_dualf[row * NB + b] = (float)(ysum[lo] / (double)cnt[lo]);
    }
}

// ---------------- launch 6: rank output (pure fp32) -------------------------
__global__ void output_kernel(const float4* __restrict__ sims4,
                              float4* __restrict__ ranks4, int M, int N) {
    int i4 = blockIdx.x * blockDim.x + threadIdx.x;
    int total4 = (M * N) >> 2;
    if (i4 >= total4) return;
    int i = i4 * 4;
    int row = i / N;
    float4 v = sims4[i4];
    const float* dr = g_dualf + row * NB;
    float4 o;
    o.x = fmaf(-10.f, v.x, -dr[sortable(v.x) >> BSHIFT]);
    o.y = fmaf(-10.f, v.y, -dr[sortable(v.y) >> BSHIFT]);
    o.z = fmaf(-10.f, v.z, -dr[sortable(v.z) >> BSHIFT]);
    o.w = fmaf(-10.f, v.w, -dr[sortable(v.w) >> BSHIFT]);
    ranks4[i4] = o;
}

// ---------------- host launch ----------------
extern "C" void kernel_launch(void* const* d_in, const int* in_sizes, int n_in,
                              void* d_out, int out_size) {
    const float* q      = (const float*)d_in[0];
    const float* corpus = (const float*)d_in[1];
    int M = in_sizes[0] / DIM;   // 16
    int N = in_sizes[1] / DIM;   // 50000
    if (M > MAXM) M = MAXM;
    if (N > MAXN) N = MAXN;

    float* sims  = (float*)d_out;
    float* ranks = sims + (size_t)M * N;

    cudaFuncSetAttribute(sim_kernel,
                         cudaFuncAttributeMaxDynamicSharedMemorySize, SMEM_DYN);
    cudaFuncSetAttribute(pavB_kernel,
                         cudaFuncAttributeMaxDynamicSharedMemorySize, PAVB_SMEM);

    zero_kernel<<<(MAXM * NB) / 256, 256>>>();                   // launch 1
    qnorm_kernel<<<MAXM, 128>>>(q, M);                           // launch 2
    bfrag_kernel<<<24, 32>>>();                                  // launch 3
    sim_kernel<<<SIM_BLOCKS, SIM_TPB, SMEM_DYN>>>(               // launch 4 (profiled)
        (const float4*)corpus, sims, M, N);
    pavB_kernel<<<M, PAVB_TPB, PAVB_SMEM>>>(N);                  // launch 5
    int total4 = (M * N) / 4;
    output_kernel<<<(total4 + 255) / 256, 256>>>(                // launch 6
        (const float4*)sims, (float4*)ranks, M, N);
}